// round 11
// baseline (speedup 1.0000x reference)
#include <cuda_runtime.h>
#include <cstdint>

// Problem constants
#define BH_  64
#define S_   1024
#define D_   64
#define QT   16      // queries per CTA
#define KC   128     // keys per chunk
#define NCH  8       // S_/KC
#define NTHREADS 512

// smem strides (floats)
#define PADK 68      // K/Q rows: QK B-loads + Q frag loads conflict-free
#define PADV 72      // V rows:   PV B-loads conflict-free

// smem layout (float offsets)
#define OFF_Q    0
#define SZ_Q     (QT*PADK)            // 1088
#define OFF_KV   (OFF_Q + SZ_Q)
#define SZ_KV    (2*KC*PADV)          // 18432 (double buffer; reused as 8 reduction slots)
#define OFF_MAXP (OFF_KV + SZ_KV)     // 16 rows x 16 warps
#define OFF_SUMP (OFF_MAXP + 256)
#define OFF_MAX  (OFF_SUMP + 256)     // 16
#define OFF_INV  (OFF_MAX + 16)       // 16
#define OFF_M    (OFF_INV + 16)       // 1024 ints
#define SMEM_FLOATS (OFF_M + S_)
#define SMEM_BYTES  (SMEM_FLOATS * 4) // 84,352 B -> 2 CTAs/SM

#define SLOT 1088    // 16 rows x 68 per reduction slot

#define NEGB (-1e30f)

__device__ __forceinline__ unsigned f2tf(float x) {
    unsigned r;
    asm("cvt.rna.tf32.f32 %0, %1;" : "=r"(r) : "f"(x));
    return r;
}

__device__ __forceinline__ void mma8(float* c, const unsigned* a, unsigned b0, unsigned b1) {
    asm volatile(
        "mma.sync.aligned.m16n8k8.row.col.f32.tf32.tf32.f32 "
        "{%0,%1,%2,%3},{%4,%5,%6,%7},{%8,%9},{%0,%1,%2,%3};\n"
        : "+f"(c[0]), "+f"(c[1]), "+f"(c[2]), "+f"(c[3])
        : "r"(a[0]), "r"(a[1]), "r"(a[2]), "r"(a[3]), "r"(b0), "r"(b1));
}

__device__ __forceinline__ void cpasync16(float* smem_dst, const float* gsrc) {
    unsigned d = (unsigned)__cvta_generic_to_shared(smem_dst);
    asm volatile("cp.async.cg.shared.global [%0],[%1],16;\n" :: "r"(d), "l"(gsrc));
}
#define CP_COMMIT() asm volatile("cp.async.commit_group;\n" ::: "memory")
#define CP_WAIT0()  asm volatile("cp.async.wait_group 0;\n" ::: "memory")
#define CP_WAIT1()  asm volatile("cp.async.wait_group 1;\n" ::: "memory")

__global__ void __launch_bounds__(NTHREADS, 2)
attn_kernel(const float* __restrict__ Q, const float* __restrict__ K,
            const float* __restrict__ V, const int* __restrict__ M,
            float* __restrict__ Out, float* __restrict__ Attn)
{
    extern __shared__ float sm[];
    float* sQ    = sm + OFF_Q;
    float* sKV   = sm + OFF_KV;   // two buffers of KC*PADV floats
    float* sMaxP = sm + OFF_MAXP; // [row][warp]
    float* sSumP = sm + OFF_SUMP; // [row][warp]
    float* sMax  = sm + OFF_MAX;  // [row]
    float* sInv  = sm + OFF_INV;  // [row]
    int*   sM    = (int*)(sm + OFF_M);

    const int bh   = blockIdx.y;
    const int q0   = blockIdx.x * QT;
    const int tid  = threadIdx.x;
    const int lane = tid & 31;
    const int warp = tid >> 5;   // 0..15
    const int g    = lane >> 2;  // fragment row group 0..7
    const int q    = lane & 3;   // fragment col group

    const float* gQ = Q + ((size_t)bh * S_ + q0) * D_;
    const float* gK = K + (size_t)bh * S_ * D_;
    const float* gV = V + (size_t)bh * S_ * D_;
    const int*   gM = M + bh * S_;
    float* gO = Out + ((size_t)bh * S_ + q0) * D_;
    float* gA = Attn ? (Attn + ((size_t)bh * S_ + q0) * S_) : nullptr;

    // ---- prologue: issue K0; stage Q + mask ----
    #pragma unroll
    for (int j = 0; j < 4; j++) {           // 128 rows x 16 f4 / 512 thr
        int f = j * NTHREADS + tid;
        int row = f >> 4, c4 = f & 15;
        cpasync16(sKV + row * PADK + c4 * 4, gK + row * D_ + c4 * 4);
    }
    CP_COMMIT();
    if (tid < 256) {                        // Q: 16 rows x 16 f4
        int row = tid >> 4, c4 = tid & 15;
        float4 val = reinterpret_cast<const float4*>(gQ)[row * (D_ / 4) + c4];
        *reinterpret_cast<float4*>(sQ + row * PADK + c4 * 4) = val;
    } else {                                // mask: 256 int4
        int i = tid - 256;
        reinterpret_cast<int4*>(sM)[i] = reinterpret_cast<const int4*>(gM)[i];
    }
    CP_WAIT0();
    __syncthreads();   // K0, sQ, sM visible

    // ---- Q (A) fragments in tf32, persistent through QK ----
    unsigned afr[8][4];
    #pragma unroll
    for (int ks = 0; ks < 8; ks++) {
        int c0 = q + ks * 8;
        afr[ks][0] = f2tf(sQ[g * PADK + c0]);
        afr[ks][1] = f2tf(sQ[(g + 8) * PADK + c0]);
        afr[ks][2] = f2tf(sQ[g * PADK + c0 + 4]);
        afr[ks][3] = f2tf(sQ[(g + 8) * PADK + c0 + 4]);
    }

    // ---- QK^T: scores stay in REGISTERS (p[c][4]); mask+max in regs ----
    const int wn = warp;    // warp owns keys wn*8..wn*8+7 of every chunk
    float p[NCH][4];
    float mlo = NEGB, mhi = NEGB;

    #pragma unroll
    for (int c = 0; c < NCH; c++) {
        if (c) { CP_WAIT0(); __syncthreads(); }
        // prefetch next K (or V0 on last iter) into the other buffer
        if (c + 1 < NCH) {
            const float* src = gK + (size_t)(c + 1) * KC * D_;
            float* dst = sKV + ((c + 1) & 1) * KC * PADV;
            #pragma unroll
            for (int j = 0; j < 4; j++) {
                int f = j * NTHREADS + tid;
                int row = f >> 4, c4 = f & 15;
                cpasync16(dst + row * PADK + c4 * 4, src + row * D_ + c4 * 4);
            }
        } else {
            float* dst = sKV;               // V0 -> buf0 (K6's buffer, safe)
            #pragma unroll
            for (int j = 0; j < 4; j++) {
                int f = j * NTHREADS + tid;
                int row = f >> 4, c4 = f & 15;
                cpasync16(dst + row * PADV + c4 * 4, gV + row * D_ + c4 * 4);
            }
        }
        CP_COMMIT();

        const float* sK = sKV + (c & 1) * KC * PADV;  // PADK stride layout
        p[c][0] = p[c][1] = p[c][2] = p[c][3] = 0.f;
        #pragma unroll
        for (int ks = 0; ks < 8; ks++) {
            int key = wn * 8 + g;
            int d0  = q + ks * 8;
            unsigned b0 = f2tf(sK[key * PADK + d0]);
            unsigned b1 = f2tf(sK[key * PADK + d0 + 4]);
            mma8(p[c], afr[ks], b0, b1);
        }
        // mask + running max, all in registers
        {
            int colb = c * KC + wn * 8 + 2 * q;
            int2 mk = *reinterpret_cast<const int2*>(&sM[colb]);
            p[c][0] = mk.x ? p[c][0] : NEGB;
            p[c][1] = mk.y ? p[c][1] : NEGB;
            p[c][2] = mk.x ? p[c][2] : NEGB;
            p[c][3] = mk.y ? p[c][3] : NEGB;
            mlo = fmaxf(mlo, fmaxf(p[c][0], p[c][1]));
            mhi = fmaxf(mhi, fmaxf(p[c][2], p[c][3]));
        }
    }

    // ---- publish per-warp row-max partials ----
    mlo = fmaxf(mlo, __shfl_xor_sync(0xffffffffu, mlo, 1));
    mlo = fmaxf(mlo, __shfl_xor_sync(0xffffffffu, mlo, 2));
    mhi = fmaxf(mhi, __shfl_xor_sync(0xffffffffu, mhi, 1));
    mhi = fmaxf(mhi, __shfl_xor_sync(0xffffffffu, mhi, 2));
    if (q == 0) {
        sMaxP[g * 16 + wn]       = mlo;
        sMaxP[(g + 8) * 16 + wn] = mhi;
    }
    __syncthreads();   // partials visible; also: all K7 reads done

    // issue V1 -> buf1 (overlaps softmax)
    {
        const float* src = gV + (size_t)KC * D_;
        float* dst = sKV + KC * PADV;
        #pragma unroll
        for (int j = 0; j < 4; j++) {
            int f = j * NTHREADS + tid;
            int row = f >> 4, c4 = f & 15;
            cpasync16(dst + row * PADV + c4 * 4, src + row * D_ + c4 * 4);
        }
        CP_COMMIT();
    }

    // finalize row maxes: warp r reduces row r (duplicate-half butterfly)
    {
        float m = sMaxP[warp * 16 + (lane & 15)];
        m = fmaxf(m, __shfl_xor_sync(0xffffffffu, m, 1));
        m = fmaxf(m, __shfl_xor_sync(0xffffffffu, m, 2));
        m = fmaxf(m, __shfl_xor_sync(0xffffffffu, m, 4));
        m = fmaxf(m, __shfl_xor_sync(0xffffffffu, m, 8));
        if (lane == 0) sMax[warp] = m;
    }
    __syncthreads();

    // ---- exp in registers + row-sum partials ----
    const float CEXP = 0.125f * 1.44269504088896340736f;  // (1/T)*log2(e)
    {
        float mg  = sMax[g];
        float mg8 = sMax[g + 8];
        float slo = 0.f, shi = 0.f;
        #pragma unroll
        for (int c = 0; c < NCH; c++) {
            float e0 = exp2f((p[c][0] - mg)  * CEXP);
            float e1 = exp2f((p[c][1] - mg)  * CEXP);
            float e2 = exp2f((p[c][2] - mg8) * CEXP);
            float e3 = exp2f((p[c][3] - mg8) * CEXP);
            p[c][0] = e0; p[c][1] = e1; p[c][2] = e2; p[c][3] = e3;
            slo += e0 + e1;
            shi += e2 + e3;
        }
        slo += __shfl_xor_sync(0xffffffffu, slo, 1);
        slo += __shfl_xor_sync(0xffffffffu, slo, 2);
        shi += __shfl_xor_sync(0xffffffffu, shi, 1);
        shi += __shfl_xor_sync(0xffffffffu, shi, 2);
        if (q == 0) {
            sSumP[g * 16 + wn]       = slo;
            sSumP[(g + 8) * 16 + wn] = shi;
        }
    }
    __syncthreads();
    {
        float s = sSumP[warp * 16 + (lane & 15)];
        s += __shfl_xor_sync(0xffffffffu, s, 1);
        s += __shfl_xor_sync(0xffffffffu, s, 2);
        s += __shfl_xor_sync(0xffffffffu, s, 4);
        s += __shfl_xor_sync(0xffffffffu, s, 8);
        if (lane == 0) sInv[warp] = 1.f / s;   // s >= 1 always
    }
    __syncthreads();
    const float invg  = sInv[g];
    const float invg8 = sInv[g + 8];

    // ---- PV: each warp's keys are its k-slice; P shuffled C-frag -> A-frag ----
    const int srcA = (lane & ~3) | (q >> 1);
    const int srcB = srcA + 2;
    const bool oddq = (lane & 1);
    float o[8][4];
    #pragma unroll
    for (int nt = 0; nt < 8; nt++) { o[nt][0] = o[nt][1] = o[nt][2] = o[nt][3] = 0.f; }

    #pragma unroll
    for (int c = 0; c < NCH; c++) {
        if (c == 0) { CP_WAIT1(); } else { CP_WAIT0(); }
        __syncthreads();   // V(c) visible; prior buffer reads done
        if (c >= 1 && c + 1 < NCH) {   // issue V(c+1)
            const float* src = gV + (size_t)(c + 1) * KC * D_;
            float* dst = sKV + ((c + 1) & 1) * KC * PADV;
            #pragma unroll
            for (int j = 0; j < 4; j++) {
                int f = j * NTHREADS + tid;
                int row = f >> 4, c4 = f & 15;
                cpasync16(dst + row * PADV + c4 * 4, src + row * D_ + c4 * 4);
            }
            CP_COMMIT();
        }
        // attn slab for chunk c straight from registers (full fp32 p)
        if (gA) {
            int colb = c * KC + wn * 8 + 2 * q;
            *reinterpret_cast<float2*>(&gA[(size_t)g * S_ + colb]) =
                make_float2(p[c][0] * invg, p[c][1] * invg);
            *reinterpret_cast<float2*>(&gA[(size_t)(g + 8) * S_ + colb]) =
                make_float2(p[c][2] * invg8, p[c][3] * invg8);
        }
        // C-frag (r, 2q+s) -> A-frag (r, k) via quad shuffles
        unsigned a[4];
        {
            float t0 = __shfl_sync(0xffffffffu, p[c][0], srcA);
            float t1 = __shfl_sync(0xffffffffu, p[c][1], srcA);
            float t2 = __shfl_sync(0xffffffffu, p[c][2], srcA);
            float t3 = __shfl_sync(0xffffffffu, p[c][3], srcA);
            float u0 = __shfl_sync(0xffffffffu, p[c][0], srcB);
            float u1 = __shfl_sync(0xffffffffu, p[c][1], srcB);
            float u2 = __shfl_sync(0xffffffffu, p[c][2], srcB);
            float u3 = __shfl_sync(0xffffffffu, p[c][3], srcB);
            a[0] = f2tf(oddq ? t1 : t0);
            a[1] = f2tf(oddq ? t3 : t2);
            a[2] = f2tf(oddq ? u1 : u0);
            a[3] = f2tf(oddq ? u3 : u2);
        }
        const float* sV = sKV + (c & 1) * KC * PADV;
        int vrow = wn * 8 + q;
        #pragma unroll
        for (int nt = 0; nt < 8; nt++) {
            int dc = nt * 8 + g;
            unsigned b0 = f2tf(sV[vrow * PADV + dc]);
            unsigned b1 = f2tf(sV[(vrow + 4) * PADV + dc]);
            mma8(o[nt], a, b0, b1);
        }
    }
    __syncthreads();   // all V reads done; KV region reusable as reduction slots

    // ---- 16-way k reduction: 8 slots, two rounds, then cooperative write ----
    {
        float* red = sKV;   // 8 slots x 1088 floats = 8704 <= 18432
        if (warp >= 8) {
            float* base = red + (warp - 8) * SLOT;
            #pragma unroll
            for (int nt = 0; nt < 8; nt++) {
                int lc = nt * 8 + 2 * q;
                *reinterpret_cast<float2*>(&base[g * PADK + lc])       = make_float2(o[nt][0], o[nt][1]);
                *reinterpret_cast<float2*>(&base[(g + 8) * PADK + lc]) = make_float2(o[nt][2], o[nt][3]);
            }
        }
        __syncthreads();
        if (warp < 8) {
            float* base = red + warp * SLOT;
            #pragma unroll
            for (int nt = 0; nt < 8; nt++) {
                int lc = nt * 8 + 2 * q;
                float2 t0 = *reinterpret_cast<const float2*>(&base[g * PADK + lc]);
                float2 t1 = *reinterpret_cast<const float2*>(&base[(g + 8) * PADK + lc]);
                o[nt][0] += t0.x; o[nt][1] += t0.y;
                o[nt][2] += t1.x; o[nt][3] += t1.y;
                *reinterpret_cast<float2*>(&base[g * PADK + lc])       = make_float2(o[nt][0], o[nt][1]);
                *reinterpret_cast<float2*>(&base[(g + 8) * PADK + lc]) = make_float2(o[nt][2], o[nt][3]);
            }
        }
        __syncthreads();
        // final: each thread sums 8 slots for one float2 of O
        {
            int r  = tid >> 5;            // 0..15
            int cc = lane * 2;            // 0..62
            float2 s = make_float2(0.f, 0.f);
            #pragma unroll
            for (int k = 0; k < 8; k++) {
                float2 t = *reinterpret_cast<const float2*>(&red[k * SLOT + r * PADK + cc]);
                s.x += t.x; s.y += t.y;
            }
            float inv = sInv[r];
            *reinterpret_cast<float2*>(&gO[(size_t)r * D_ + cc]) =
                make_float2(s.x * inv, s.y * inv);
        }
    }
}

extern "C" void kernel_launch(void* const* d_in, const int* in_sizes, int n_in,
                              void* d_out, int out_size)
{
    const float* q    = (const float*)d_in[0];
    const float* k    = (const float*)d_in[1];
    const float* v    = (const float*)d_in[2];
    const int*   mask = (const int*)d_in[3];
    float* out = (float*)d_out;

    const size_t out_elems  = (size_t)BH_ * S_ * D_;   //  4,194,304
    const size_t attn_elems = (size_t)BH_ * S_ * S_;   // 67,108,864
    float* attn = ((size_t)out_size >= out_elems + attn_elems) ? (out + out_elems) : nullptr;

    cudaFuncSetAttribute(attn_kernel, cudaFuncAttributeMaxDynamicSharedMemorySize, SMEM_BYTES);

    dim3 grid(S_ / QT, BH_);
    attn_kernel<<<grid, NTHREADS, SMEM_BYTES>>>(q, k, v, mask, out, attn);
}

// round 14
// speedup vs baseline: 1.0080x; 1.0080x over previous
#include <cuda_runtime.h>
#include <cstdint>

// Problem constants
#define BH_  64
#define S_   1024
#define D_   64
#define QT   16      // queries per CTA
#define KC   128     // keys per chunk
#define NCH  8       // S_/KC
#define NTHREADS 512

// smem strides (floats)
#define PADK 68      // K/Q rows: QK B-loads + Q frag loads conflict-free
#define PADV 72      // V rows:   PV B-loads conflict-free

// smem layout (float offsets)
#define OFF_Q    0
#define SZ_Q     (QT*PADK)            // 1088
#define OFF_KV   (OFF_Q + SZ_Q)
#define SZ_KV    (2*KC*PADV)          // 18432 (double buffer; reused as 8 reduction slots)
#define OFF_MAXP (OFF_KV + SZ_KV)     // 16 rows x 16 warps
#define OFF_SUMP (OFF_MAXP + 256)
#define OFF_MAX  (OFF_SUMP + 256)     // 16
#define OFF_INV  (OFF_MAX + 16)       // 16
#define OFF_M    (OFF_INV + 16)       // 1024 ints
#define SMEM_FLOATS (OFF_M + S_)
#define SMEM_BYTES  (SMEM_FLOATS * 4) // 84,352 B

#define SLOT 1088    // 16 rows x 68 per reduction slot

#define NEGB (-1e30f)

__device__ __forceinline__ unsigned f2tf(float x) {
    unsigned r;
    asm("cvt.rna.tf32.f32 %0, %1;" : "=r"(r) : "f"(x));
    return r;
}

__device__ __forceinline__ void mma8(float* c, const unsigned* a, unsigned b0, unsigned b1) {
    asm volatile(
        "mma.sync.aligned.m16n8k8.row.col.f32.tf32.tf32.f32 "
        "{%0,%1,%2,%3},{%4,%5,%6,%7},{%8,%9},{%0,%1,%2,%3};\n"
        : "+f"(c[0]), "+f"(c[1]), "+f"(c[2]), "+f"(c[3])
        : "r"(a[0]), "r"(a[1]), "r"(a[2]), "r"(a[3]), "r"(b0), "r"(b1));
}

__device__ __forceinline__ void cpasync16(float* smem_dst, const float* gsrc) {
    unsigned d = (unsigned)__cvta_generic_to_shared(smem_dst);
    asm volatile("cp.async.cg.shared.global [%0],[%1],16;\n" :: "r"(d), "l"(gsrc));
}
#define CP_COMMIT() asm volatile("cp.async.commit_group;\n" ::: "memory")
#define CP_WAIT0()  asm volatile("cp.async.wait_group 0;\n" ::: "memory")
#define CP_WAIT1()  asm volatile("cp.async.wait_group 1;\n" ::: "memory")

// R12 KEY CHANGE: minBlocksPerMultiprocessor 2 -> 1.
// Live state (~110 floats: p[8][4] + afr[8][4] + o[8][4] + working) needs
// ~110 regs; the old (512,2) bound capped regs at 64 and spilled ~40+ regs
// to local memory (R11: L1 64%, DRAM 19%, 414us). With (512,1) ptxas gets
// 128 regs (512*128 = full RF), zero spills, occ = 16 warps.
__global__ void __launch_bounds__(NTHREADS, 1)
attn_kernel(const float* __restrict__ Q, const float* __restrict__ K,
            const float* __restrict__ V, const int* __restrict__ M,
            float* __restrict__ Out, float* __restrict__ Attn)
{
    extern __shared__ float sm[];
    float* sQ    = sm + OFF_Q;
    float* sKV   = sm + OFF_KV;   // two buffers of KC*PADV floats
    float* sMaxP = sm + OFF_MAXP; // [row][warp]
    float* sSumP = sm + OFF_SUMP; // [row][warp]
    float* sMax  = sm + OFF_MAX;  // [row]
    float* sInv  = sm + OFF_INV;  // [row]
    int*   sM    = (int*)(sm + OFF_M);

    const int bh   = blockIdx.y;
    const int q0   = blockIdx.x * QT;
    const int tid  = threadIdx.x;
    const int lane = tid & 31;
    const int warp = tid >> 5;   // 0..15
    const int g    = lane >> 2;  // fragment row group 0..7
    const int q    = lane & 3;   // fragment col group

    const float* gQ = Q + ((size_t)bh * S_ + q0) * D_;
    const float* gK = K + (size_t)bh * S_ * D_;
    const float* gV = V + (size_t)bh * S_ * D_;
    const int*   gM = M + bh * S_;
    float* gO = Out + ((size_t)bh * S_ + q0) * D_;
    float* gA = Attn ? (Attn + ((size_t)bh * S_ + q0) * S_) : nullptr;

    // ---- prologue: issue K0; stage Q + mask ----
    #pragma unroll
    for (int j = 0; j < 4; j++) {           // 128 rows x 16 f4 / 512 thr
        int f = j * NTHREADS + tid;
        int row = f >> 4, c4 = f & 15;
        cpasync16(sKV + row * PADK + c4 * 4, gK + row * D_ + c4 * 4);
    }
    CP_COMMIT();
    if (tid < 256) {                        // Q: 16 rows x 16 f4
        int row = tid >> 4, c4 = tid & 15;
        float4 val = reinterpret_cast<const float4*>(gQ)[row * (D_ / 4) + c4];
        *reinterpret_cast<float4*>(sQ + row * PADK + c4 * 4) = val;
    } else {                                // mask: 256 int4
        int i = tid - 256;
        reinterpret_cast<int4*>(sM)[i] = reinterpret_cast<const int4*>(gM)[i];
    }
    CP_WAIT0();
    __syncthreads();   // K0, sQ, sM visible

    // ---- Q (A) fragments in tf32, persistent through QK ----
    unsigned afr[8][4];
    #pragma unroll
    for (int ks = 0; ks < 8; ks++) {
        int c0 = q + ks * 8;
        afr[ks][0] = f2tf(sQ[g * PADK + c0]);
        afr[ks][1] = f2tf(sQ[(g + 8) * PADK + c0]);
        afr[ks][2] = f2tf(sQ[g * PADK + c0 + 4]);
        afr[ks][3] = f2tf(sQ[(g + 8) * PADK + c0 + 4]);
    }

    // ---- QK^T: scores stay in REGISTERS (p[c][4]); mask+max in regs ----
    const int wn = warp;    // warp owns keys wn*8..wn*8+7 of every chunk
    float p[NCH][4];
    float mlo = NEGB, mhi = NEGB;

    #pragma unroll
    for (int c = 0; c < NCH; c++) {
        if (c) { CP_WAIT0(); __syncthreads(); }
        // prefetch next K (or V0 on last iter) into the other buffer
        if (c + 1 < NCH) {
            const float* src = gK + (size_t)(c + 1) * KC * D_;
            float* dst = sKV + ((c + 1) & 1) * KC * PADV;
            #pragma unroll
            for (int j = 0; j < 4; j++) {
                int f = j * NTHREADS + tid;
                int row = f >> 4, c4 = f & 15;
                cpasync16(dst + row * PADK + c4 * 4, src + row * D_ + c4 * 4);
            }
        } else {
            float* dst = sKV;               // V0 -> buf0 (K6's buffer, safe)
            #pragma unroll
            for (int j = 0; j < 4; j++) {
                int f = j * NTHREADS + tid;
                int row = f >> 4, c4 = f & 15;
                cpasync16(dst + row * PADV + c4 * 4, gV + row * D_ + c4 * 4);
            }
        }
        CP_COMMIT();

        const float* sK = sKV + (c & 1) * KC * PADV;  // PADK stride layout
        p[c][0] = p[c][1] = p[c][2] = p[c][3] = 0.f;
        #pragma unroll
        for (int ks = 0; ks < 8; ks++) {
            int key = wn * 8 + g;
            int d0  = q + ks * 8;
            unsigned b0 = f2tf(sK[key * PADK + d0]);
            unsigned b1 = f2tf(sK[key * PADK + d0 + 4]);
            mma8(p[c], afr[ks], b0, b1);
        }
        // mask + running max, all in registers
        {
            int colb = c * KC + wn * 8 + 2 * q;
            int2 mk = *reinterpret_cast<const int2*>(&sM[colb]);
            p[c][0] = mk.x ? p[c][0] : NEGB;
            p[c][1] = mk.y ? p[c][1] : NEGB;
            p[c][2] = mk.x ? p[c][2] : NEGB;
            p[c][3] = mk.y ? p[c][3] : NEGB;
            mlo = fmaxf(mlo, fmaxf(p[c][0], p[c][1]));
            mhi = fmaxf(mhi, fmaxf(p[c][2], p[c][3]));
        }
    }

    // ---- publish per-warp row-max partials ----
    mlo = fmaxf(mlo, __shfl_xor_sync(0xffffffffu, mlo, 1));
    mlo = fmaxf(mlo, __shfl_xor_sync(0xffffffffu, mlo, 2));
    mhi = fmaxf(mhi, __shfl_xor_sync(0xffffffffu, mhi, 1));
    mhi = fmaxf(mhi, __shfl_xor_sync(0xffffffffu, mhi, 2));
    if (q == 0) {
        sMaxP[g * 16 + wn]       = mlo;
        sMaxP[(g + 8) * 16 + wn] = mhi;
    }
    __syncthreads();   // partials visible; also: all K7 reads done

    // issue V1 -> buf1 (overlaps softmax)
    {
        const float* src = gV + (size_t)KC * D_;
        float* dst = sKV + KC * PADV;
        #pragma unroll
        for (int j = 0; j < 4; j++) {
            int f = j * NTHREADS + tid;
            int row = f >> 4, c4 = f & 15;
            cpasync16(dst + row * PADV + c4 * 4, src + row * D_ + c4 * 4);
        }
        CP_COMMIT();
    }

    // finalize row maxes: warp r reduces row r (duplicate-half butterfly)
    {
        float m = sMaxP[warp * 16 + (lane & 15)];
        m = fmaxf(m, __shfl_xor_sync(0xffffffffu, m, 1));
        m = fmaxf(m, __shfl_xor_sync(0xffffffffu, m, 2));
        m = fmaxf(m, __shfl_xor_sync(0xffffffffu, m, 4));
        m = fmaxf(m, __shfl_xor_sync(0xffffffffu, m, 8));
        if (lane == 0) sMax[warp] = m;
    }
    __syncthreads();

    // ---- exp in registers + row-sum partials ----
    const float CEXP = 0.125f * 1.44269504088896340736f;  // (1/T)*log2(e)
    {
        float mg  = sMax[g];
        float mg8 = sMax[g + 8];
        float slo = 0.f, shi = 0.f;
        #pragma unroll
        for (int c = 0; c < NCH; c++) {
            float e0 = exp2f((p[c][0] - mg)  * CEXP);
            float e1 = exp2f((p[c][1] - mg)  * CEXP);
            float e2 = exp2f((p[c][2] - mg8) * CEXP);
            float e3 = exp2f((p[c][3] - mg8) * CEXP);
            p[c][0] = e0; p[c][1] = e1; p[c][2] = e2; p[c][3] = e3;
            slo += e0 + e1;
            shi += e2 + e3;
        }
        slo += __shfl_xor_sync(0xffffffffu, slo, 1);
        slo += __shfl_xor_sync(0xffffffffu, slo, 2);
        shi += __shfl_xor_sync(0xffffffffu, shi, 1);
        shi += __shfl_xor_sync(0xffffffffu, shi, 2);
        if (q == 0) {
            sSumP[g * 16 + wn]       = slo;
            sSumP[(g + 8) * 16 + wn] = shi;
        }
    }
    __syncthreads();
    {
        float s = sSumP[warp * 16 + (lane & 15)];
        s += __shfl_xor_sync(0xffffffffu, s, 1);
        s += __shfl_xor_sync(0xffffffffu, s, 2);
        s += __shfl_xor_sync(0xffffffffu, s, 4);
        s += __shfl_xor_sync(0xffffffffu, s, 8);
        if (lane == 0) sInv[warp] = 1.f / s;   // s >= 1 always
    }
    __syncthreads();
    const float invg  = sInv[g];
    const float invg8 = sInv[g + 8];

    // ---- PV: each warp's keys are its k-slice; P shuffled C-frag -> A-frag ----
    const int srcA = (lane & ~3) | (q >> 1);
    const int srcB = srcA + 2;
    const bool oddq = (lane & 1);
    float o[8][4];
    #pragma unroll
    for (int nt = 0; nt < 8; nt++) { o[nt][0] = o[nt][1] = o[nt][2] = o[nt][3] = 0.f; }

    #pragma unroll
    for (int c = 0; c < NCH; c++) {
        if (c == 0) { CP_WAIT1(); } else { CP_WAIT0(); }
        __syncthreads();   // V(c) visible; prior buffer reads done
        if (c >= 1 && c + 1 < NCH) {   // issue V(c+1)
            const float* src = gV + (size_t)(c + 1) * KC * D_;
            float* dst = sKV + ((c + 1) & 1) * KC * PADV;
            #pragma unroll
            for (int j = 0; j < 4; j++) {
                int f = j * NTHREADS + tid;
                int row = f >> 4, c4 = f & 15;
                cpasync16(dst + row * PADV + c4 * 4, src + row * D_ + c4 * 4);
            }
            CP_COMMIT();
        }
        // attn slab for chunk c straight from registers (full fp32 p)
        if (gA) {
            int colb = c * KC + wn * 8 + 2 * q;
            *reinterpret_cast<float2*>(&gA[(size_t)g * S_ + colb]) =
                make_float2(p[c][0] * invg, p[c][1] * invg);
            *reinterpret_cast<float2*>(&gA[(size_t)(g + 8) * S_ + colb]) =
                make_float2(p[c][2] * invg8, p[c][3] * invg8);
        }
        // C-frag (r, 2q+s) -> A-frag (r, k) via quad shuffles
        unsigned a[4];
        {
            float t0 = __shfl_sync(0xffffffffu, p[c][0], srcA);
            float t1 = __shfl_sync(0xffffffffu, p[c][1], srcA);
            float t2 = __shfl_sync(0xffffffffu, p[c][2], srcA);
            float t3 = __shfl_sync(0xffffffffu, p[c][3], srcA);
            float u0 = __shfl_sync(0xffffffffu, p[c][0], srcB);
            float u1 = __shfl_sync(0xffffffffu, p[c][1], srcB);
            float u2 = __shfl_sync(0xffffffffu, p[c][2], srcB);
            float u3 = __shfl_sync(0xffffffffu, p[c][3], srcB);
            a[0] = f2tf(oddq ? t1 : t0);
            a[1] = f2tf(oddq ? t3 : t2);
            a[2] = f2tf(oddq ? u1 : u0);
            a[3] = f2tf(oddq ? u3 : u2);
        }
        const float* sV = sKV + (c & 1) * KC * PADV;
        int vrow = wn * 8 + q;
        #pragma unroll
        for (int nt = 0; nt < 8; nt++) {
            int dc = nt * 8 + g;
            unsigned b0 = f2tf(sV[vrow * PADV + dc]);
            unsigned b1 = f2tf(sV[(vrow + 4) * PADV + dc]);
            mma8(o[nt], a, b0, b1);
        }
    }
    __syncthreads();   // all V reads done; KV region reusable as reduction slots

    // ---- 16-way k reduction: 8 slots, two rounds, then cooperative write ----
    {
        float* red = sKV;   // 8 slots x 1088 floats = 8704 <= 18432
        if (warp >= 8) {
            float* base = red + (warp - 8) * SLOT;
            #pragma unroll
            for (int nt = 0; nt < 8; nt++) {
                int lc = nt * 8 + 2 * q;
                *reinterpret_cast<float2*>(&base[g * PADK + lc])       = make_float2(o[nt][0], o[nt][1]);
                *reinterpret_cast<float2*>(&base[(g + 8) * PADK + lc]) = make_float2(o[nt][2], o[nt][3]);
            }
        }
        __syncthreads();
        if (warp < 8) {
            float* base = red + warp * SLOT;
            #pragma unroll
            for (int nt = 0; nt < 8; nt++) {
                int lc = nt * 8 + 2 * q;
                float2 t0 = *reinterpret_cast<const float2*>(&base[g * PADK + lc]);
                float2 t1 = *reinterpret_cast<const float2*>(&base[(g + 8) * PADK + lc]);
                o[nt][0] += t0.x; o[nt][1] += t0.y;
                o[nt][2] += t1.x; o[nt][3] += t1.y;
                *reinterpret_cast<float2*>(&base[g * PADK + lc])       = make_float2(o[nt][0], o[nt][1]);
                *reinterpret_cast<float2*>(&base[(g + 8) * PADK + lc]) = make_float2(o[nt][2], o[nt][3]);
            }
        }
        __syncthreads();
        // final: each thread sums 8 slots for one float2 of O
        {
            int r  = tid >> 5;            // 0..15
            int cc = lane * 2;            // 0..62
            float2 s = make_float2(0.f, 0.f);
            #pragma unroll
            for (int k = 0; k < 8; k++) {
                float2 t = *reinterpret_cast<const float2*>(&red[k * SLOT + r * PADK + cc]);
                s.x += t.x; s.y += t.y;
            }
            float inv = sInv[r];
            *reinterpret_cast<float2*>(&gO[(size_t)r * D_ + cc]) =
                make_float2(s.x * inv, s.y * inv);
        }
    }
}

extern "C" void kernel_launch(void* const* d_in, const int* in_sizes, int n_in,
                              void* d_out, int out_size)
{
    const float* q    = (const float*)d_in[0];
    const float* k    = (const float*)d_in[1];
    const float* v    = (const float*)d_in[2];
    const int*   mask = (const int*)d_in[3];
    float* out = (float*)d_out;

    const size_t out_elems  = (size_t)BH_ * S_ * D_;   //  4,194,304
    const size_t attn_elems = (size_t)BH_ * S_ * S_;   // 67,108,864
    float* attn = ((size_t)out_size >= out_elems + attn_elems) ? (out + out_elems) : nullptr;

    cudaFuncSetAttribute(attn_kernel, cudaFuncAttributeMaxDynamicSharedMemorySize, SMEM_BYTES);

    dim3 grid(S_ / QT, BH_);
    attn_kernel<<<grid, NTHREADS, SMEM_BYTES>>>(q, k, v, mask, out, attn);
}

// round 15
// speedup vs baseline: 1.3233x; 1.3128x over previous
#include <cuda_runtime.h>
#include <cstdint>

// Problem constants
#define BH_  64
#define S_   1024
#define D_   64
#define QT   32      // queries per CTA
#define KC   128     // keys per chunk
#define NCH  8       // S_/KC
#define NTHREADS 1024

// smem strides (floats)
#define PADK 68      // K/Q rows: QK B-loads + Q frag loads conflict-free
#define PADV 72      // V rows:   PV B-loads conflict-free
#define PADS 1028    // score rows: PV A-loads conflict-free
#define RSTR 36      // reduction partial row stride
#define RSLOT 576    // 16 rows x 36 per reduction slot

// smem layout (float offsets)
#define OFF_Q    0
#define SZ_Q     (QT*PADK)            // 2176
#define OFF_KV   (OFF_Q + SZ_Q)
#define SZ_KV    (2*KC*PADV)          // 18432 (double buffer)
#define OFF_S    (OFF_KV + SZ_KV)
#define SZ_S     (QT*PADS)            // 32896 (reused: 32*RSLOT=18432 reduction)
#define OFF_MAXP (OFF_S + SZ_S)       // 32 rows x 16 warps
#define OFF_MAX  (OFF_MAXP + 512)     // 32
#define OFF_INV  (OFF_MAX + 32)       // 32
#define OFF_M    (OFF_INV + 32)       // 1024 ints
#define SMEM_FLOATS (OFF_M + S_)
#define SMEM_BYTES  (SMEM_FLOATS * 4) // 222,336 B < 227 KB

#define NEGB (-1e30f)

__device__ __forceinline__ unsigned f2tf(float x) {
    unsigned r;
    asm("cvt.rna.tf32.f32 %0, %1;" : "=r"(r) : "f"(x));
    return r;
}

__device__ __forceinline__ void mma8(float* c, const unsigned* a, unsigned b0, unsigned b1) {
    asm volatile(
        "mma.sync.aligned.m16n8k8.row.col.f32.tf32.tf32.f32 "
        "{%0,%1,%2,%3},{%4,%5,%6,%7},{%8,%9},{%0,%1,%2,%3};\n"
        : "+f"(c[0]), "+f"(c[1]), "+f"(c[2]), "+f"(c[3])
        : "r"(a[0]), "r"(a[1]), "r"(a[2]), "r"(a[3]), "r"(b0), "r"(b1));
}

__device__ __forceinline__ void cpasync16(float* smem_dst, const float* gsrc) {
    unsigned d = (unsigned)__cvta_generic_to_shared(smem_dst);
    asm volatile("cp.async.cg.shared.global [%0],[%1],16;\n" :: "r"(d), "l"(gsrc));
}
#define CP_COMMIT() asm volatile("cp.async.commit_group;\n" ::: "memory")
#define CP_WAIT0()  asm volatile("cp.async.wait_group 0;\n" ::: "memory")
#define CP_WAIT1()  asm volatile("cp.async.wait_group 1;\n" ::: "memory")

__global__ void __launch_bounds__(NTHREADS, 1)
attn_kernel(const float* __restrict__ Q, const float* __restrict__ K,
            const float* __restrict__ V, const int* __restrict__ M,
            float* __restrict__ Out, float* __restrict__ Attn)
{
    extern __shared__ float sm[];
    float* sQ    = sm + OFF_Q;
    float* sKV   = sm + OFF_KV;   // two buffers of KC*PADV floats
    float* sS    = sm + OFF_S;    // 32 x 1024 scores/probs; later reduction scratch
    float* sMaxP = sm + OFF_MAXP; // [row][warp-of-16]
    float* sMax  = sm + OFF_MAX;  // [row]
    float* sInv  = sm + OFF_INV;  // [row]
    int*   sM    = (int*)(sm + OFF_M);

    const int bh   = blockIdx.y;
    const int q0   = blockIdx.x * QT;
    const int tid  = threadIdx.x;
    const int lane = tid & 31;
    const int warp = tid >> 5;   // 0..31
    const int g    = lane >> 2;  // fragment row group 0..7
    const int q    = lane & 3;   // fragment col group

    const float* gQ = Q + ((size_t)bh * S_ + q0) * D_;
    const float* gK = K + (size_t)bh * S_ * D_;
    const float* gV = V + (size_t)bh * S_ * D_;
    const int*   gM = M + bh * S_;
    float* gO = Out + ((size_t)bh * S_ + q0) * D_;
    float* gA = Attn ? (Attn + ((size_t)bh * S_ + q0) * S_) : nullptr;

    // ---- prologue: issue K0; stage Q + mask ----
    #pragma unroll
    for (int j = 0; j < 2; j++) {           // 128 rows x 16 f4 = 2048 f4 / 1024 thr
        int f = j * NTHREADS + tid;
        int row = f >> 4, c4 = f & 15;
        cpasync16(sKV + row * PADK + c4 * 4, gK + row * D_ + c4 * 4);
    }
    CP_COMMIT();
    if (tid < 512) {                        // Q: 32 rows x 16 f4
        int row = tid >> 4, c4 = tid & 15;
        float4 val = reinterpret_cast<const float4*>(gQ)[row * (D_ / 4) + c4];
        *reinterpret_cast<float4*>(sQ + row * PADK + c4 * 4) = val;
    } else {                                // mask: 512 int2
        int i = tid - 512;
        reinterpret_cast<int2*>(sM)[i] = reinterpret_cast<const int2*>(gM)[i];
    }
    CP_WAIT0();
    __syncthreads();   // K0, sQ, sM visible

    // ---- Q (A) fragments in tf32, persistent through QK ----
    const int qb = (warp >> 4) * 16;   // m-tile rows qb..qb+15
    unsigned afr[8][4];
    #pragma unroll
    for (int ks = 0; ks < 8; ks++) {
        int c0 = q + ks * 8;
        afr[ks][0] = f2tf(sQ[(qb + g) * PADK + c0]);
        afr[ks][1] = f2tf(sQ[(qb + g + 8) * PADK + c0]);
        afr[ks][2] = f2tf(sQ[(qb + g) * PADK + c0 + 4]);
        afr[ks][3] = f2tf(sQ[(qb + g + 8) * PADK + c0 + 4]);
    }

    // ---- QK^T: 32 warps = 2m x 16n; running row-max in regs ----
    const int wn = warp & 15;    // keys wn*8..wn*8+7 of each chunk
    float mlo = NEGB, mhi = NEGB;
    for (int c = 0; c < NCH; c++) {
        if (c) { CP_WAIT0(); __syncthreads(); }
        // prefetch next K chunk, or V0 on the last iteration
        if (c + 1 < NCH) {
            const float* src = gK + (size_t)(c + 1) * KC * D_;
            float* dst = sKV + ((c + 1) & 1) * KC * PADV;
            #pragma unroll
            for (int j = 0; j < 2; j++) {
                int f = j * NTHREADS + tid;
                int row = f >> 4, c4 = f & 15;
                cpasync16(dst + row * PADK + c4 * 4, src + row * D_ + c4 * 4);
            }
        } else {
            float* dst = sKV;               // V0 -> buf0 (compute reads buf1)
            #pragma unroll
            for (int j = 0; j < 2; j++) {
                int f = j * NTHREADS + tid;
                int row = f >> 4, c4 = f & 15;
                cpasync16(dst + row * PADV + c4 * 4, gV + row * D_ + c4 * 4);
            }
        }
        CP_COMMIT();

        const float* sK = sKV + (c & 1) * KC * PADV;  // PADK-stride layout
        float acc[4] = {0.f, 0.f, 0.f, 0.f};
        #pragma unroll
        for (int ks = 0; ks < 8; ks++) {
            int key = wn * 8 + g;
            int d0  = q + ks * 8;
            unsigned b0 = f2tf(sK[key * PADK + d0]);
            unsigned b1 = f2tf(sK[key * PADK + d0 + 4]);
            mma8(acc, afr[ks], b0, b1);
        }
        // mask + score write + running max
        {
            int col = c * KC + wn * 8 + 2 * q;
            int2 mk = *reinterpret_cast<const int2*>(&sM[col]);
            float s0 = mk.x ? acc[0] : NEGB;
            float s1 = mk.y ? acc[1] : NEGB;
            float s2 = mk.x ? acc[2] : NEGB;
            float s3 = mk.y ? acc[3] : NEGB;
            *reinterpret_cast<float2*>(&sS[(qb + g) * PADS + col])     = make_float2(s0, s1);
            *reinterpret_cast<float2*>(&sS[(qb + g + 8) * PADS + col]) = make_float2(s2, s3);
            mlo = fmaxf(mlo, fmaxf(s0, s1));
            mhi = fmaxf(mhi, fmaxf(s2, s3));
        }
    }
    // reduce running maxes across the 4 q-lanes; publish per-warp partials
    mlo = fmaxf(mlo, __shfl_xor_sync(0xffffffffu, mlo, 1));
    mlo = fmaxf(mlo, __shfl_xor_sync(0xffffffffu, mlo, 2));
    mhi = fmaxf(mhi, __shfl_xor_sync(0xffffffffu, mhi, 1));
    mhi = fmaxf(mhi, __shfl_xor_sync(0xffffffffu, mhi, 2));
    if (q == 0) {
        sMaxP[(qb + g) * 16 + wn]     = mlo;
        sMaxP[(qb + g + 8) * 16 + wn] = mhi;
    }
    __syncthreads();   // scores + partials visible; all K7 (buf1) reads done

    // issue V1 -> buf1 (overlaps max-finalize + softmax)
    {
        const float* src = gV + (size_t)KC * D_;
        float* dst = sKV + KC * PADV;
        #pragma unroll
        for (int j = 0; j < 2; j++) {
            int f = j * NTHREADS + tid;
            int row = f >> 4, c4 = f & 15;
            cpasync16(dst + row * PADV + c4 * 4, src + row * D_ + c4 * 4);
        }
        CP_COMMIT();
    }

    // finalize row maxes: warp r reduces row r (both 16-lane halves duplicate)
    {
        float m = sMaxP[warp * 16 + (lane & 15)];
        m = fmaxf(m, __shfl_xor_sync(0xffffffffu, m, 1));
        m = fmaxf(m, __shfl_xor_sync(0xffffffffu, m, 2));
        m = fmaxf(m, __shfl_xor_sync(0xffffffffu, m, 4));
        m = fmaxf(m, __shfl_xor_sync(0xffffffffu, m, 8));
        if (lane == 0) sMax[warp] = m;
    }
    __syncthreads();

    // ---- softmax: warp r owns row r (32 lanes x 8 f4); attn written here ----
    {
        const int r = warp;
        const float CEXP = 0.125f * 1.44269504088896340736f;  // (1/T)*log2(e)
        const float m = sMax[r];
        float4* rowS = reinterpret_cast<float4*>(sS + (size_t)r * PADS);

        float l = 0.f;
        #pragma unroll
        for (int j = 0; j < 8; j++) {
            int i4 = lane + j * 32;
            float4 s = rowS[i4];
            float4 p;
            p.x = exp2f((s.x - m) * CEXP);
            p.y = exp2f((s.y - m) * CEXP);
            p.z = exp2f((s.z - m) * CEXP);
            p.w = exp2f((s.w - m) * CEXP);
            rowS[i4] = p;              // unnormalized p kept for PV
            l += (p.x + p.y) + (p.z + p.w);
        }
        l += __shfl_xor_sync(0xffffffffu, l, 1);
        l += __shfl_xor_sync(0xffffffffu, l, 2);
        l += __shfl_xor_sync(0xffffffffu, l, 4);
        l += __shfl_xor_sync(0xffffffffu, l, 8);
        l += __shfl_xor_sync(0xffffffffu, l, 16);
        float invl = 1.f / l;          // l >= 1 always (max contributes 1)
        if (lane == 0) sInv[r] = invl;

        if (gA) {
            float4* rowA = reinterpret_cast<float4*>(gA + (size_t)r * S_);
            #pragma unroll
            for (int j = 0; j < 8; j++) {
                int i4 = lane + j * 32;
                float4 p = rowS[i4];
                p.x *= invl; p.y *= invl; p.z *= invl; p.w *= invl;
                rowA[i4] = p;          // normalized attn
            }
        }
    }
    __syncthreads();   // probs + sInv visible to all warps

    // ---- P(unnorm) @ V: 32 warps = 2m x 2n x 8k ----
    const int wn1 = (warp >> 3) & 1;   // cols wn1*32..+31
    const int wk  = warp & 7;          // keys wk*16..+15 within chunk
    float o[4][4];
    #pragma unroll
    for (int nt = 0; nt < 4; nt++) { o[nt][0] = o[nt][1] = o[nt][2] = o[nt][3] = 0.f; }

    for (int c = 0; c < NCH; c++) {
        if (c == 0) { CP_WAIT1(); } else { CP_WAIT0(); }
        __syncthreads();   // V(c) visible; prior buffer reads done
        if (c >= 1 && c + 1 < NCH) {   // issue V(c+1)
            const float* src = gV + (size_t)(c + 1) * KC * D_;
            float* dst = sKV + ((c + 1) & 1) * KC * PADV;
            #pragma unroll
            for (int j = 0; j < 2; j++) {
                int f = j * NTHREADS + tid;
                int row = f >> 4, c4 = f & 15;
                cpasync16(dst + row * PADV + c4 * 4, src + row * D_ + c4 * 4);
            }
            CP_COMMIT();
        }
        const float* sV = sKV + (c & 1) * KC * PADV;
        #pragma unroll
        for (int kk = 0; kk < 2; kk++) {
            unsigned a[4];
            int kc = c * KC + wk * 16 + kk * 8 + q;
            a[0] = f2tf(sS[(qb + g) * PADS + kc]);
            a[1] = f2tf(sS[(qb + g + 8) * PADS + kc]);
            a[2] = f2tf(sS[(qb + g) * PADS + kc + 4]);
            a[3] = f2tf(sS[(qb + g + 8) * PADS + kc + 4]);
            int key = wk * 16 + kk * 8 + q;
            #pragma unroll
            for (int nt = 0; nt < 4; nt++) {
                int dc = wn1 * 32 + nt * 8 + g;
                unsigned b0 = f2tf(sV[key * PADV + dc]);
                unsigned b1 = f2tf(sV[(key + 4) * PADV + dc]);
                mma8(o[nt], a, b0, b1);
            }
        }
    }
    __syncthreads();   // all PV reads of sS/sKV done; sS reusable

    // ---- 8-way k reduction through smem (reuse sS), fold invl, write O ----
    {
        float* red = sS;   // 32 slots x 576 floats = 18432 <= SZ_S
        float* base = red + warp * RSLOT;
        #pragma unroll
        for (int nt = 0; nt < 4; nt++) {
            int lc = nt * 8 + 2 * q;
            *reinterpret_cast<float2*>(&base[g * RSTR + lc])       = make_float2(o[nt][0], o[nt][1]);
            *reinterpret_cast<float2*>(&base[(g + 8) * RSTR + lc]) = make_float2(o[nt][2], o[nt][3]);
        }
    }
    __syncthreads();
    {
        const float* red = sS;
        int r  = tid >> 5;            // 0..31
        int cc = lane * 2;            // 0..62
        int wmr = r >> 4, row16 = r & 15;
        int nh  = cc >> 5, lc = cc & 31;
        const float* pb = red + (size_t)(wmr * 16 + nh * 8) * RSLOT + row16 * RSTR + lc;
        float2 s = make_float2(0.f, 0.f);
        #pragma unroll
        for (int k = 0; k < 8; k++) {
            float2 t = *reinterpret_cast<const float2*>(pb + (size_t)k * RSLOT);
            s.x += t.x; s.y += t.y;
        }
        float inv = sInv[r];
        *reinterpret_cast<float2*>(&gO[(size_t)r * D_ + cc]) =
            make_float2(s.x * inv, s.y * inv);
    }
}

extern "C" void kernel_launch(void* const* d_in, const int* in_sizes, int n_in,
                              void* d_out, int out_size)
{
    const float* q    = (const float*)d_in[0];
    const float* k    = (const float*)d_in[1];
    const float* v    = (const float*)d_in[2];
    const int*   mask = (const int*)d_in[3];
    float* out = (float*)d_out;

    const size_t out_elems  = (size_t)BH_ * S_ * D_;   //  4,194,304
    const size_t attn_elems = (size_t)BH_ * S_ * S_;   // 67,108,864
    float* attn = ((size_t)out_size >= out_elems + attn_elems) ? (out + out_elems) : nullptr;

    cudaFuncSetAttribute(attn_kernel, cudaFuncAttributeMaxDynamicSharedMemorySize, SMEM_BYTES);

    dim3 grid(S_ / QT, BH_);
    attn_kernel<<<grid, NTHREADS, SMEM_BYTES>>>(q, k, v, mask, out, attn);
}